// round 3
// baseline (speedup 1.0000x reference)
#include <cuda_runtime.h>

#define BATCH 4
#define TFULL 2048
#define CDIM  1024
#define NHEAD 16
#define HDIM  64

// Scratch (allocation-free rule: __device__ globals)
__device__ float g_qkv[(size_t)BATCH * TFULL * 3 * CDIM];  // (B,T,3C) ~100.7 MB
__device__ float g_y[(size_t)BATCH * TFULL * CDIM];        // (B,T,C)  ~33.5 MB

// ---------------------------------------------------------------------------
// NT GEMM: C[m,n] = sum_k A[m,k] * B[n,k]
// A: M x K row-major, B: N x K row-major (i.e. C = A @ B^T)
// 128x128x16 tile, 256 threads, 8x8 per-thread register tile.
// ---------------------------------------------------------------------------
__global__ void __launch_bounds__(256) gemm_nt(const float* __restrict__ A,
                                               const float* __restrict__ B,
                                               float* __restrict__ C,
                                               int M, int N, int K)
{
    __shared__ float As[16][128];   // A^T tile: As[k][m]
    __shared__ float Bs[16][128];   // B^T tile: Bs[k][n]

    const int tid = threadIdx.x;
    const int tx = tid & 15;        // col group (8 cols each)
    const int ty = tid >> 4;        // row group (8 rows each)
    const int bm = blockIdx.y * 128;
    const int bn = blockIdx.x * 128;

    float acc[8][8];
#pragma unroll
    for (int i = 0; i < 8; ++i)
#pragma unroll
        for (int j = 0; j < 8; ++j) acc[i][j] = 0.f;

    for (int k0 = 0; k0 < K; k0 += 16) {
#pragma unroll
        for (int l = 0; l < 2; ++l) {
            int i = tid + l * 256;       // 0..511
            int row = i >> 2;            // 0..127
            int kk = (i & 3) * 4;        // 0,4,8,12
            float4 a = *(const float4*)(A + (size_t)(bm + row) * K + k0 + kk);
            As[kk + 0][row] = a.x; As[kk + 1][row] = a.y;
            As[kk + 2][row] = a.z; As[kk + 3][row] = a.w;
            float4 b = *(const float4*)(B + (size_t)(bn + row) * K + k0 + kk);
            Bs[kk + 0][row] = b.x; Bs[kk + 1][row] = b.y;
            Bs[kk + 2][row] = b.z; Bs[kk + 3][row] = b.w;
        }
        __syncthreads();
#pragma unroll
        for (int k = 0; k < 16; ++k) {
            float ra[8], rb[8];
            *(float4*)&ra[0] = *(const float4*)&As[k][ty * 8];
            *(float4*)&ra[4] = *(const float4*)&As[k][ty * 8 + 4];
            *(float4*)&rb[0] = *(const float4*)&Bs[k][tx * 8];
            *(float4*)&rb[4] = *(const float4*)&Bs[k][tx * 8 + 4];
#pragma unroll
            for (int i = 0; i < 8; ++i)
#pragma unroll
                for (int j = 0; j < 8; ++j)
                    acc[i][j] += ra[i] * rb[j];
        }
        __syncthreads();
    }

#pragma unroll
    for (int i = 0; i < 8; ++i) {
        float* cp = C + (size_t)(bm + ty * 8 + i) * N + bn + tx * 8;
        *(float4*)cp       = make_float4(acc[i][0], acc[i][1], acc[i][2], acc[i][3]);
        *(float4*)(cp + 4) = make_float4(acc[i][4], acc[i][5], acc[i][6], acc[i][7]);
    }
}

// ---------------------------------------------------------------------------
// Causal flash attention, fp32. One block = one (b, h, 64-row q-tile).
// 256 threads: 16x16 thread grid, each thread owns a 4x4 fragment.
// Q and K stored transposed in smem with XOR-(d&60) swizzle so that the
// transpose stores are ~2-way conflicted but ALL inner-loop reads are
// conflict-free float4s. P overwrites the K buffer (transposed, same swizzle).
// ---------------------------------------------------------------------------
__global__ void __launch_bounds__(256) flash_attn(const float* __restrict__ qkv,
                                                  float* __restrict__ y)
{
    __shared__ float Qt[64 * 64];   // Q^T, swizzled: Qt[d*64 + (r ^ (d&60))]
    __shared__ float KPt[64 * 64];  // K^T (swizzled), then P^T (swizzled)
    __shared__ float Vs[64 * 64];   // V row-major: Vs[k*64 + c]

    const int qt = (gridDim.x - 1) - blockIdx.x;  // big q-tiles first (balance)
    const int bh = blockIdx.y;
    const int b = bh >> 4;
    const int h = bh & 15;
    const int q0 = qt * 64;
    const int tid = threadIdx.x;
    const int tx = tid & 15;
    const int ty = tid >> 4;
    const size_t rs = 3 * CDIM;   // qkv row stride

    const float* qb = qkv + (size_t)b * TFULL * rs + (size_t)h * HDIM;
    const float* kb = qb + CDIM;
    const float* vb = qb + 2 * CDIM;

    // Load Q tile transposed + swizzled, folding in 1/sqrt(D) = 0.125
#pragma unroll
    for (int l = 0; l < 4; ++l) {
        int i = tid + l * 256;     // 0..1023
        int r = i >> 4;            // 0..63
        int d4 = (i & 15) * 4;     // 0..60
        float4 q = *(const float4*)(qb + (size_t)(q0 + r) * rs + d4);
        Qt[(d4 + 0) * 64 + (r ^ ((d4 + 0) & 60))] = q.x * 0.125f;
        Qt[(d4 + 1) * 64 + (r ^ ((d4 + 1) & 60))] = q.y * 0.125f;
        Qt[(d4 + 2) * 64 + (r ^ ((d4 + 2) & 60))] = q.z * 0.125f;
        Qt[(d4 + 3) * 64 + (r ^ ((d4 + 3) & 60))] = q.w * 0.125f;
    }

    float m_i[4], l_i[4], o[4][4];
#pragma unroll
    for (int i = 0; i < 4; ++i) {
        m_i[i] = -1e30f;
        l_i[i] = 0.f;
#pragma unroll
        for (int j = 0; j < 4; ++j) o[i][j] = 0.f;
    }

    for (int kt = 0; kt <= qt; ++kt) {
        const int k0 = kt * 64;
        __syncthreads();   // prior-iter PV reads done (and Q stores ordered)

        // Load K^T (swizzled) and V (row-major)
#pragma unroll
        for (int l = 0; l < 4; ++l) {
            int i = tid + l * 256;
            int r = i >> 4;
            int d4 = (i & 15) * 4;
            float4 kx = *(const float4*)(kb + (size_t)(k0 + r) * rs + d4);
            KPt[(d4 + 0) * 64 + (r ^ ((d4 + 0) & 60))] = kx.x;
            KPt[(d4 + 1) * 64 + (r ^ ((d4 + 1) & 60))] = kx.y;
            KPt[(d4 + 2) * 64 + (r ^ ((d4 + 2) & 60))] = kx.z;
            KPt[(d4 + 3) * 64 + (r ^ ((d4 + 3) & 60))] = kx.w;
            float4 vx = *(const float4*)(vb + (size_t)(k0 + r) * rs + d4);
            *(float4*)&Vs[r * 64 + d4] = vx;
        }
        __syncthreads();

        // S = (Q * scale) @ K^T  — thread fragment s[i][j]
        float s[4][4];
#pragma unroll
        for (int i = 0; i < 4; ++i)
#pragma unroll
            for (int j = 0; j < 4; ++j) s[i][j] = 0.f;

#pragma unroll 16
        for (int d = 0; d < 64; ++d) {
            float4 qv = *(const float4*)&Qt[d * 64 + ((ty * 4) ^ (d & 60))];
            float4 kv = *(const float4*)&KPt[d * 64 + ((tx * 4) ^ (d & 60))];
            s[0][0] += qv.x * kv.x; s[0][1] += qv.x * kv.y; s[0][2] += qv.x * kv.z; s[0][3] += qv.x * kv.w;
            s[1][0] += qv.y * kv.x; s[1][1] += qv.y * kv.y; s[1][2] += qv.y * kv.z; s[1][3] += qv.y * kv.w;
            s[2][0] += qv.z * kv.x; s[2][1] += qv.z * kv.y; s[2][2] += qv.z * kv.z; s[2][3] += qv.z * kv.w;
            s[3][0] += qv.w * kv.x; s[3][1] += qv.w * kv.y; s[3][2] += qv.w * kv.z; s[3][3] += qv.w * kv.w;
        }

        // Causal mask on the diagonal tile
        if (kt == qt) {
#pragma unroll
            for (int i = 0; i < 4; ++i)
#pragma unroll
                for (int j = 0; j < 4; ++j)
                    if (tx * 4 + j > ty * 4 + i) s[i][j] = -1e30f;
        }

        // Row max over the 64-wide tile (reduce over the 16 tx lanes)
        float mt[4], ls[4];
#pragma unroll
        for (int i = 0; i < 4; ++i)
            mt[i] = fmaxf(fmaxf(s[i][0], s[i][1]), fmaxf(s[i][2], s[i][3]));
#pragma unroll
        for (int off = 1; off < 16; off <<= 1)
#pragma unroll
            for (int i = 0; i < 4; ++i)
                mt[i] = fmaxf(mt[i], __shfl_xor_sync(0xffffffffu, mt[i], off));

#pragma unroll
        for (int i = 0; i < 4; ++i) {
            float mn = fmaxf(m_i[i], mt[i]);
            float sc = __expf(m_i[i] - mn);
            m_i[i] = mn;
            l_i[i] *= sc;
#pragma unroll
            for (int j = 0; j < 4; ++j) o[i][j] *= sc;
            float lsum = 0.f;
#pragma unroll
            for (int j = 0; j < 4; ++j) {
                float p = __expf(s[i][j] - mn);
                s[i][j] = p;
                lsum += p;
            }
            ls[i] = lsum;
        }
#pragma unroll
        for (int off = 1; off < 16; off <<= 1)
#pragma unroll
            for (int i = 0; i < 4; ++i)
                ls[i] += __shfl_xor_sync(0xffffffffu, ls[i], off);
#pragma unroll
        for (int i = 0; i < 4; ++i) l_i[i] += ls[i];

        __syncthreads();   // everyone done reading KPt as K^T
        // Store P^T (swizzled): Pt[n][r], n = kv index
#pragma unroll
        for (int j = 0; j < 4; ++j) {
            int n = tx * 4 + j;
#pragma unroll
            for (int i = 0; i < 4; ++i)
                KPt[n * 64 + ((ty * 4 + i) ^ (n & 60))] = s[i][j];
        }
        __syncthreads();

        // O += P @ V
#pragma unroll 16
        for (int k = 0; k < 64; ++k) {
            float4 pv = *(const float4*)&KPt[k * 64 + ((ty * 4) ^ (k & 60))];
            float4 vv = *(const float4*)&Vs[k * 64 + tx * 4];
            o[0][0] += pv.x * vv.x; o[0][1] += pv.x * vv.y; o[0][2] += pv.x * vv.z; o[0][3] += pv.x * vv.w;
            o[1][0] += pv.y * vv.x; o[1][1] += pv.y * vv.y; o[1][2] += pv.y * vv.z; o[1][3] += pv.y * vv.w;
            o[2][0] += pv.z * vv.x; o[2][1] += pv.z * vv.y; o[2][2] += pv.z * vv.z; o[2][3] += pv.z * vv.w;
            o[3][0] += pv.w * vv.x; o[3][1] += pv.w * vv.y; o[3][2] += pv.w * vv.z; o[3][3] += pv.w * vv.w;
        }
    }

    // Epilogue: O / l, write (B,T,C) with heads interleaved
    float* yb = y + (size_t)b * TFULL * CDIM + (size_t)h * HDIM;
#pragma unroll
    for (int i = 0; i < 4; ++i) {
        int r = q0 + ty * 4 + i;
        float inv = 1.f / l_i[i];
        *(float4*)(yb + (size_t)r * CDIM + tx * 4) =
            make_float4(o[i][0] * inv, o[i][1] * inv, o[i][2] * inv, o[i][3] * inv);
    }
}

// ---------------------------------------------------------------------------
extern "C" void kernel_launch(void* const* d_in, const int* in_sizes, int n_in,
                              void* d_out, int out_size)
{
    const float* x      = (const float*)d_in[0];   // (B,T,C)
    const float* w_attn = (const float*)d_in[1];   // (3C,C)
    const float* w_proj = (const float*)d_in[2];   // (C,C)
    float* out = (float*)d_out;                    // (B,T,C)

    float* qkv = nullptr;
    float* yb  = nullptr;
    cudaGetSymbolAddress((void**)&qkv, g_qkv);
    cudaGetSymbolAddress((void**)&yb, g_y);

    const int M = BATCH * TFULL;          // 8192

    // 1) qkv = x @ w_attn^T   : (8192 x 3072)
    gemm_nt<<<dim3(3 * CDIM / 128, M / 128), 256>>>(x, w_attn, qkv, M, 3 * CDIM, CDIM);

    // 2) y = causal_attention(qkv)
    flash_attn<<<dim3(TFULL / 64, BATCH * NHEAD), 256>>>(qkv, yb);

    // 3) out = y @ w_proj^T   : (8192 x 1024)
    gemm_nt<<<dim3(CDIM / 128, M / 128), 256>>>(yb, w_proj, out, M, CDIM, CDIM);
}

// round 4
// speedup vs baseline: 1.4681x; 1.4681x over previous
#include <cuda_runtime.h>
#include <cstdint>

#define BATCH 4
#define TFULL 2048
#define CDIM  1024
#define NHEAD 16
#define HDIM  64

// Scratch (allocation-free rule: __device__ globals)
__device__ float g_qkv[(size_t)BATCH * TFULL * 3 * CDIM];  // (B,T,3C) ~100.7 MB
__device__ float g_y[(size_t)BATCH * TFULL * CDIM];        // (B,T,C)  ~33.5 MB

__device__ __forceinline__ uint32_t f2tf32(float f) {
    uint32_t u;
    asm("cvt.rna.tf32.f32 %0, %1;" : "=r"(u) : "f"(f));
    return u;
}

// ---------------------------------------------------------------------------
// NT GEMM on tf32 tensor cores: C[m,n] = sum_k A[m,k] * B[n,k]
// 128x128 block tile, k-chunk 16. 8 warps, warp tile 64(M)x32(N).
// mma.sync.aligned.m16n8k8.row.col.f32.tf32.tf32.f32
// Smem holds operands in fragment-native layout:
//   AF[mt(8)][ks(2)][lane(32)][reg(4)]  (m16 tiles of A)
//   BF[nt(16)][ks(2)][lane(32)][reg(2)] (n8 tiles of B)
// so per-thread fragment loads are single LDS.128 / LDS.64, conflict-free.
// ---------------------------------------------------------------------------
__global__ void __launch_bounds__(256) gemm_nt_tc(const float* __restrict__ A,
                                                  const float* __restrict__ B,
                                                  float* __restrict__ C,
                                                  int M, int N, int K)
{
    __shared__ uint32_t AF[8 * 2 * 32 * 4];   // 8 KB
    __shared__ uint32_t BF[16 * 2 * 32 * 2];  // 8 KB

    const int tid  = threadIdx.x;
    const int lane = tid & 31;
    const int warp = tid >> 5;
    const int wy = warp >> 2;      // 0..1 (M)
    const int wx = warp & 3;       // 0..3 (N)
    const int bm = blockIdx.y * 128;
    const int bn = blockIdx.x * 128;

    float acc[4][4][4];            // [mt][nt][creg]
#pragma unroll
    for (int i = 0; i < 4; ++i)
#pragma unroll
        for (int j = 0; j < 4; ++j)
#pragma unroll
            for (int r = 0; r < 4; ++r) acc[i][j][r] = 0.f;

    // Loader mapping: each thread owns 2 float4 of A and 2 of B per k-chunk.
    const int lrow0 = tid >> 2;          // 0..63
    const int lkk   = (tid & 3) * 4;     // 0,4,8,12

    float4 pa[2], pb[2];
    // initial prefetch (k0 = 0)
#pragma unroll
    for (int l = 0; l < 2; ++l) {
        int row = lrow0 + l * 64;
        pa[l] = *(const float4*)(A + (size_t)(bm + row) * K + lkk);
        pb[l] = *(const float4*)(B + (size_t)(bn + row) * K + lkk);
    }

    for (int k0 = 0; k0 < K; k0 += 16) {
        // ---- store prefetched chunk into fragment-layout smem ----
#pragma unroll
        for (int l = 0; l < 2; ++l) {
            int row = lrow0 + l * 64;
            const float va[4] = {pa[l].x, pa[l].y, pa[l].z, pa[l].w};
            const float vb[4] = {pb[l].x, pb[l].y, pb[l].z, pb[l].w};
            // A: mt = row>>4, r = row&15 ; c_full = lkk + j
            {
                int mt = row >> 4, r = row & 15;
                int ks = lkk >> 3;            // lkk multiple of 4 -> same ks for j=0..3
                int chalf = (lkk & 7) >> 2;   // c>=4 ?
                int reg = (r >> 3) + (chalf << 1);
                int base = ((mt * 2 + ks) * 32 + (r & 7) * 4) * 4 + reg;
#pragma unroll
                for (int j = 0; j < 4; ++j)
                    AF[base + j * 4] = f2tf32(va[j]);   // lane advances with j
            }
            // B: nt = row>>3, n = row&7 ; k_full = lkk + j
            {
                int nt = row >> 3, n = row & 7;
                int ks = lkk >> 3;
                int reg = (lkk & 7) >> 2;     // k>>2 within kstep
                int base = ((nt * 2 + ks) * 32 + n * 4) * 2 + reg;
#pragma unroll
                for (int j = 0; j < 4; ++j)
                    BF[base + j * 2] = f2tf32(vb[j]);   // lane advances with j
            }
        }
        __syncthreads();

        // ---- prefetch next chunk ----
        if (k0 + 16 < K) {
#pragma unroll
            for (int l = 0; l < 2; ++l) {
                int row = lrow0 + l * 64;
                pa[l] = *(const float4*)(A + (size_t)(bm + row) * K + k0 + 16 + lkk);
                pb[l] = *(const float4*)(B + (size_t)(bn + row) * K + k0 + 16 + lkk);
            }
        }

        // ---- compute: 2 k-steps of 8 ----
#pragma unroll
        for (int ks = 0; ks < 2; ++ks) {
            uint32_t a[4][4], b[4][2];
#pragma unroll
            for (int mt = 0; mt < 4; ++mt) {
                int mtg = wy * 4 + mt;
                *(uint4*)a[mt] = *(const uint4*)&AF[((mtg * 2 + ks) * 32 + lane) * 4];
            }
#pragma unroll
            for (int nt = 0; nt < 4; ++nt) {
                int ntg = wx * 4 + nt;
                *(uint2*)b[nt] = *(const uint2*)&BF[((ntg * 2 + ks) * 32 + lane) * 2];
            }
#pragma unroll
            for (int mt = 0; mt < 4; ++mt)
#pragma unroll
                for (int nt = 0; nt < 4; ++nt) {
                    asm volatile(
                        "mma.sync.aligned.m16n8k8.row.col.f32.tf32.tf32.f32 "
                        "{%0,%1,%2,%3}, {%4,%5,%6,%7}, {%8,%9}, {%0,%1,%2,%3};"
                        : "+f"(acc[mt][nt][0]), "+f"(acc[mt][nt][1]),
                          "+f"(acc[mt][nt][2]), "+f"(acc[mt][nt][3])
                        : "r"(a[mt][0]), "r"(a[mt][1]), "r"(a[mt][2]), "r"(a[mt][3]),
                          "r"(b[nt][0]), "r"(b[nt][1]));
                }
        }
        __syncthreads();
    }

    // ---- epilogue: fragment layout -> global ----
#pragma unroll
    for (int mt = 0; mt < 4; ++mt) {
        int row0 = bm + wy * 64 + mt * 16 + (lane >> 2);
#pragma unroll
        for (int nt = 0; nt < 4; ++nt) {
            int col = bn + wx * 32 + nt * 8 + 2 * (lane & 3);
            *(float2*)(C + (size_t)row0 * N + col) =
                make_float2(acc[mt][nt][0], acc[mt][nt][1]);
            *(float2*)(C + (size_t)(row0 + 8) * N + col) =
                make_float2(acc[mt][nt][2], acc[mt][nt][3]);
        }
    }
}

// ---------------------------------------------------------------------------
// Causal flash attention, fp32 (unchanged from round 3).
// ---------------------------------------------------------------------------
__global__ void __launch_bounds__(256) flash_attn(const float* __restrict__ qkv,
                                                  float* __restrict__ y)
{
    __shared__ float Qt[64 * 64];
    __shared__ float KPt[64 * 64];
    __shared__ float Vs[64 * 64];

    const int qt = (gridDim.x - 1) - blockIdx.x;
    const int bh = blockIdx.y;
    const int b = bh >> 4;
    const int h = bh & 15;
    const int q0 = qt * 64;
    const int tid = threadIdx.x;
    const int tx = tid & 15;
    const int ty = tid >> 4;
    const size_t rs = 3 * CDIM;

    const float* qb = qkv + (size_t)b * TFULL * rs + (size_t)h * HDIM;
    const float* kb = qb + CDIM;
    const float* vb = qb + 2 * CDIM;

#pragma unroll
    for (int l = 0; l < 4; ++l) {
        int i = tid + l * 256;
        int r = i >> 4;
        int d4 = (i & 15) * 4;
        float4 q = *(const float4*)(qb + (size_t)(q0 + r) * rs + d4);
        Qt[(d4 + 0) * 64 + (r ^ ((d4 + 0) & 60))] = q.x * 0.125f;
        Qt[(d4 + 1) * 64 + (r ^ ((d4 + 1) & 60))] = q.y * 0.125f;
        Qt[(d4 + 2) * 64 + (r ^ ((d4 + 2) & 60))] = q.z * 0.125f;
        Qt[(d4 + 3) * 64 + (r ^ ((d4 + 3) & 60))] = q.w * 0.125f;
    }

    float m_i[4], l_i[4], o[4][4];
#pragma unroll
    for (int i = 0; i < 4; ++i) {
        m_i[i] = -1e30f;
        l_i[i] = 0.f;
#pragma unroll
        for (int j = 0; j < 4; ++j) o[i][j] = 0.f;
    }

    for (int kt = 0; kt <= qt; ++kt) {
        const int k0 = kt * 64;
        __syncthreads();

#pragma unroll
        for (int l = 0; l < 4; ++l) {
            int i = tid + l * 256;
            int r = i >> 4;
            int d4 = (i & 15) * 4;
            float4 kx = *(const float4*)(kb + (size_t)(k0 + r) * rs + d4);
            KPt[(d4 + 0) * 64 + (r ^ ((d4 + 0) & 60))] = kx.x;
            KPt[(d4 + 1) * 64 + (r ^ ((d4 + 1) & 60))] = kx.y;
            KPt[(d4 + 2) * 64 + (r ^ ((d4 + 2) & 60))] = kx.z;
            KPt[(d4 + 3) * 64 + (r ^ ((d4 + 3) & 60))] = kx.w;
            float4 vx = *(const float4*)(vb + (size_t)(k0 + r) * rs + d4);
            *(float4*)&Vs[r * 64 + d4] = vx;
        }
        __syncthreads();

        float s[4][4];
#pragma unroll
        for (int i = 0; i < 4; ++i)
#pragma unroll
            for (int j = 0; j < 4; ++j) s[i][j] = 0.f;

#pragma unroll 16
        for (int d = 0; d < 64; ++d) {
            float4 qv = *(const float4*)&Qt[d * 64 + ((ty * 4) ^ (d & 60))];
            float4 kv = *(const float4*)&KPt[d * 64 + ((tx * 4) ^ (d & 60))];
            s[0][0] += qv.x * kv.x; s[0][1] += qv.x * kv.y; s[0][2] += qv.x * kv.z; s[0][3] += qv.x * kv.w;
            s[1][0] += qv.y * kv.x; s[1][1] += qv.y * kv.y; s[1][2] += qv.y * kv.z; s[1][3] += qv.y * kv.w;
            s[2][0] += qv.z * kv.x; s[2][1] += qv.z * kv.y; s[2][2] += qv.z * kv.z; s[2][3] += qv.z * kv.w;
            s[3][0] += qv.w * kv.x; s[3][1] += qv.w * kv.y; s[3][2] += qv.w * kv.z; s[3][3] += qv.w * kv.w;
        }

        if (kt == qt) {
#pragma unroll
            for (int i = 0; i < 4; ++i)
#pragma unroll
                for (int j = 0; j < 4; ++j)
                    if (tx * 4 + j > ty * 4 + i) s[i][j] = -1e30f;
        }

        float mt[4], ls[4];
#pragma unroll
        for (int i = 0; i < 4; ++i)
            mt[i] = fmaxf(fmaxf(s[i][0], s[i][1]), fmaxf(s[i][2], s[i][3]));
#pragma unroll
        for (int off = 1; off < 16; off <<= 1)
#pragma unroll
            for (int i = 0; i < 4; ++i)
                mt[i] = fmaxf(mt[i], __shfl_xor_sync(0xffffffffu, mt[i], off));

#pragma unroll
        for (int i = 0; i < 4; ++i) {
            float mn = fmaxf(m_i[i], mt[i]);
            float sc = __expf(m_i[i] - mn);
            m_i[i] = mn;
            l_i[i] *= sc;
#pragma unroll
            for (int j = 0; j < 4; ++j) o[i][j] *= sc;
            float lsum = 0.f;
#pragma unroll
            for (int j = 0; j < 4; ++j) {
                float p = __expf(s[i][j] - mn);
                s[i][j] = p;
                lsum += p;
            }
            ls[i] = lsum;
        }
#pragma unroll
        for (int off = 1; off < 16; off <<= 1)
#pragma unroll
            for (int i = 0; i < 4; ++i)
                ls[i] += __shfl_xor_sync(0xffffffffu, ls[i], off);
#pragma unroll
        for (int i = 0; i < 4; ++i) l_i[i] += ls[i];

        __syncthreads();
#pragma unroll
        for (int j = 0; j < 4; ++j) {
            int n = tx * 4 + j;
#pragma unroll
            for (int i = 0; i < 4; ++i)
                KPt[n * 64 + ((ty * 4 + i) ^ (n & 60))] = s[i][j];
        }
        __syncthreads();

#pragma unroll 16
        for (int k = 0; k < 64; ++k) {
            float4 pv = *(const float4*)&KPt[k * 64 + ((ty * 4) ^ (k & 60))];
            float4 vv = *(const float4*)&Vs[k * 64 + tx * 4];
            o[0][0] += pv.x * vv.x; o[0][1] += pv.x * vv.y; o[0][2] += pv.x * vv.z; o[0][3] += pv.x * vv.w;
            o[1][0] += pv.y * vv.x; o[1][1] += pv.y * vv.y; o[1][2] += pv.y * vv.z; o[1][3] += pv.y * vv.w;
            o[2][0] += pv.z * vv.x; o[2][1] += pv.z * vv.y; o[2][2] += pv.z * vv.z; o[2][3] += pv.z * vv.w;
            o[3][0] += pv.w * vv.x; o[3][1] += pv.w * vv.y; o[3][2] += pv.w * vv.z; o[3][3] += pv.w * vv.w;
        }
    }

    float* yb = y + (size_t)b * TFULL * CDIM + (size_t)h * HDIM;
#pragma unroll
    for (int i = 0; i < 4; ++i) {
        int r = q0 + ty * 4 + i;
        float inv = 1.f / l_i[i];
        *(float4*)(yb + (size_t)r * CDIM + tx * 4) =
            make_float4(o[i][0] * inv, o[i][1] * inv, o[i][2] * inv, o[i][3] * inv);
    }
}

// ---------------------------------------------------------------------------
extern "C" void kernel_launch(void* const* d_in, const int* in_sizes, int n_in,
                              void* d_out, int out_size)
{
    const float* x      = (const float*)d_in[0];   // (B,T,C)
    const float* w_attn = (const float*)d_in[1];   // (3C,C)
    const float* w_proj = (const float*)d_in[2];   // (C,C)
    float* out = (float*)d_out;                    // (B,T,C)

    float* qkv = nullptr;
    float* yb  = nullptr;
    cudaGetSymbolAddress((void**)&qkv, g_qkv);
    cudaGetSymbolAddress((void**)&yb, g_y);

    const int M = BATCH * TFULL;          // 8192

    // 1) qkv = x @ w_attn^T   : (8192 x 3072)
    gemm_nt_tc<<<dim3(3 * CDIM / 128, M / 128), 256>>>(x, w_attn, qkv, M, 3 * CDIM, CDIM);

    // 2) y = causal_attention(qkv)
    flash_attn<<<dim3(TFULL / 64, BATCH * NHEAD), 256>>>(qkv, yb);

    // 3) out = y @ w_proj^T   : (8192 x 1024)
    gemm_nt_tc<<<dim3(CDIM / 128, M / 128), 256>>>(yb, w_proj, out, M, CDIM, CDIM);
}